// round 5
// baseline (speedup 1.0000x reference)
#include <cuda_runtime.h>
#include <cstdint>

// ProcessorNet reduction (exact up to fp reassociation):
//   z_0 = x@wd.T + bd                              [B,16]
//   z_{t+1} = z_t + relu(z_t) @ P_t + c,  P_t = diag(prog_t) @ A,  A = wu.T@wd.T
//   R = sum_t relu(z_t)*prog_t ;  out = x + R@wu.T + 64*bu
// TWO rows per thread; each z packed column-wise as 8x f32x2.
// P (with c as a 17th row) is read once per step and feeds both rows.

#define HDIM 128
#define LSTEPS 64

struct Consts {
    float Pc[LSTEPS][17][16];  // Pc[t][j][i]=prog[t][j]*A[j][i]; row16 = c
    float wd2[128][16];        // wd2[h][i] = wd[i][h]
    float prog[LSTEPS][16];
    float wupc[64][16][2];     // wupc[hp][j] = {wu[2hp][j], wu[2hp+1][j]}
    float bd[16];
    float bu64[128];           // 64*bu[h]
    float A[16][16];           // scratch
    float c[16];               // scratch
};
__device__ Consts g_c;

// shared layout (floats):
//   region0: max(P 64*17*16=17408, tile 256*33=8448) = 17408
//   persist: wd2 2048 + prog 1024 + wupc 2048 + bd 16 + bu64 128 = 5264
#define REGION0_FLOATS 17408
#define PERSIST_FLOATS 5264
#define SMEM_FLOATS (REGION0_FLOATS + PERSIST_FLOATS)  // 22672
#define SMEM_BYTES (SMEM_FLOATS * 4)                   // 90688

__global__ void setup_kernel(const float* __restrict__ prog,
                             const float* __restrict__ wd,
                             const float* __restrict__ bd,
                             const float* __restrict__ wu,
                             const float* __restrict__ bu) {
    int tid = threadIdx.x;  // 256 threads, 1 block
    {   // A[j][i] = sum_h wu[h][j] * wd[i][h]
        int j = tid >> 4, i = tid & 15;
        float s = 0.f;
        #pragma unroll 8
        for (int h = 0; h < HDIM; ++h) s += wu[h * 16 + j] * wd[i * HDIM + h];
        g_c.A[j][i] = s;
    }
    if (tid < 16) {
        int i = tid;
        float s = 0.f;
        #pragma unroll 8
        for (int h = 0; h < HDIM; ++h) s += bu[h] * wd[i * HDIM + h];
        g_c.c[i] = s;
        g_c.bd[i] = bd[i];
    }
    for (int idx = tid; idx < LSTEPS * 16; idx += 256)
        g_c.prog[idx >> 4][idx & 15] = prog[idx];
    for (int idx = tid; idx < 128 * 16; idx += 256) {
        int h = idx >> 4, i = idx & 15;
        g_c.wd2[h][i] = wd[i * HDIM + h];
    }
    for (int idx = tid; idx < 64 * 16; idx += 256) {
        int hp = idx >> 4, j = idx & 15;
        g_c.wupc[hp][j][0] = wu[(2 * hp) * 16 + j];
        g_c.wupc[hp][j][1] = wu[(2 * hp + 1) * 16 + j];
    }
    for (int idx = tid; idx < 128; idx += 256) g_c.bu64[idx] = 64.f * bu[idx];
    __syncthreads();
    for (int idx = tid; idx < LSTEPS * 17 * 16; idx += 256) {
        int t = idx / 272, rem = idx % 272;
        int j = rem >> 4, i = rem & 15;
        g_c.Pc[t][j][i] = (j < 16) ? g_c.prog[t][j] * g_c.A[j][i] : g_c.c[i];
    }
}

// ---- packed f32x2 helpers ----
typedef unsigned long long u64;

__device__ __forceinline__ u64 pk(float x, float y) {
    u64 r; asm("mov.b64 %0, {%1, %2};" : "=l"(r) : "f"(x), "f"(y)); return r;
}
__device__ __forceinline__ void upk(u64 v, float& x, float& y) {
    asm("mov.b64 {%0, %1}, %2;" : "=f"(x), "=f"(y) : "l"(v));
}
__device__ __forceinline__ u64 fma2(u64 a, u64 b, u64 c) {
    u64 d; asm("fma.rn.f32x2 %0, %1, %2, %3;" : "=l"(d) : "l"(a), "l"(b), "l"(c)); return d;
}

// phase A: accumulate z += x_row @ wd.T for one 256-row group
__device__ __forceinline__ void phaseA(const float* __restrict__ xg,
                                       float* tile, const float* s_wd2,
                                       u64 z2[8], int tid) {
    for (int ch = 0; ch < 4; ++ch) {
        __syncthreads();
        for (int f = tid; f < 8192; f += 256) {
            int r = f >> 5, c = f & 31;
            tile[r * 33 + c] = xg[(long)r * HDIM + ch * 32 + c];
        }
        __syncthreads();
        #pragma unroll
        for (int c = 0; c < 32; ++c) {
            float xv = tile[tid * 33 + c];
            u64 xs = pk(xv, xv);
            const ulonglong2* w = (const ulonglong2*)(s_wd2 + (ch * 32 + c) * 16);
            #pragma unroll
            for (int kk = 0; kk < 4; ++kk) {
                ulonglong2 wv = w[kk];
                z2[2 * kk]     = fma2(xs, wv.x, z2[2 * kk]);
                z2[2 * kk + 1] = fma2(xs, wv.y, z2[2 * kk + 1]);
            }
        }
    }
}

// phase C: out_row = x_row + R @ wu.T + 64*bu for one 256-row group
__device__ __forceinline__ void phaseC(const float* __restrict__ xg,
                                       float* __restrict__ og,
                                       float* tile, const float* s_wupc,
                                       const float* s_bu,
                                       const u64 Racc2[8], int tid) {
    u64 Rs[16];
    #pragma unroll
    for (int k = 0; k < 8; ++k) {
        float r0, r1;
        upk(Racc2[k], r0, r1);
        Rs[2 * k]     = pk(r0, r0);
        Rs[2 * k + 1] = pk(r1, r1);
    }
    for (int ch = 0; ch < 4; ++ch) {
        __syncthreads();
        #pragma unroll
        for (int hp = 0; hp < 16; ++hp) {
            int h2 = ch * 16 + hp;
            u64 acc = *(const u64*)(s_bu + h2 * 2);
            const ulonglong2* urow = (const ulonglong2*)(s_wupc + h2 * 32);
            #pragma unroll
            for (int jj = 0; jj < 8; ++jj) {
                ulonglong2 u = urow[jj];
                acc = fma2(Rs[2 * jj],     u.x, acc);
                acc = fma2(Rs[2 * jj + 1], u.y, acc);
            }
            float y0, y1;
            upk(acc, y0, y1);
            tile[tid * 33 + 2 * hp]     = y0;
            tile[tid * 33 + 2 * hp + 1] = y1;
        }
        __syncthreads();
        for (int f = tid; f < 8192; f += 256) {
            int r = f >> 5, c = f & 31;
            long g = (long)r * HDIM + ch * 32 + c;
            og[g] = xg[g] + tile[r * 33 + c];
        }
    }
}

__global__ __launch_bounds__(256, 2)
void proc_kernel(const float* __restrict__ x, float* __restrict__ out) {
    extern __shared__ float sm[];
    float* region0 = sm;                      // tile (A/C) | P (phase B)
    float* s_wd2   = sm + REGION0_FLOATS;     // 2048
    float* s_prog  = s_wd2 + 2048;            // 1024
    float* s_wupc  = s_prog + 1024;           // 2048
    float* s_bd    = s_wupc + 2048;           // 16
    float* s_bu    = s_bd + 16;               // 128

    int tid = threadIdx.x;

    // copy persistent consts (wd2..bu64 contiguous in Consts)
    {
        const float4* src = (const float4*)&g_c.wd2[0][0];
        float4* dst = (float4*)(sm + REGION0_FLOATS);
        for (int i = tid; i < PERSIST_FLOATS / 4; i += 256) dst[i] = src[i];
    }
    __syncthreads();

    long row0 = (long)blockIdx.x * 512;       // 512 rows per block (2/thread)
    const float* xa = x + row0 * HDIM;
    const float* xb = xa + 256L * HDIM;
    float* oa = out + row0 * HDIM;
    float* ob = oa + 256L * HDIM;

    u64 za[8], zb[8];
    #pragma unroll
    for (int k = 0; k < 8; ++k) {
        u64 b = *(const u64*)(s_bd + 2 * k);
        za[k] = b; zb[k] = b;
    }

    // ---- phase A for both row groups ----
    phaseA(xa, region0, s_wd2, za, tid);
    phaseA(xb, region0, s_wd2, zb, tid);

    // ---- stage full P (64 steps) into smem ----
    __syncthreads();
    {
        const float4* src = (const float4*)&g_c.Pc[0][0][0];
        float4* dst = (float4*)region0;
        for (int i = tid; i < REGION0_FLOATS / 4; i += 256) dst[i] = src[i];
    }
    __syncthreads();

    // ---- phase B: 64-step recurrence, P reads shared by both rows ----
    u64 Ra[8], Rb[8];
    #pragma unroll
    for (int k = 0; k < 8; ++k) { Ra[k] = 0ull; Rb[k] = 0ull; }
    const u64 one2 = pk(1.f, 1.f);

    #pragma unroll 1
    for (int t = 0; t < LSTEPS; ++t) {
        float ma[16], mb[16];
        #pragma unroll
        for (int k = 0; k < 8; ++k) {
            float u, v;
            upk(za[k], u, v);
            ma[2 * k] = fmaxf(u, 0.f); ma[2 * k + 1] = fmaxf(v, 0.f);
            upk(zb[k], u, v);
            mb[2 * k] = fmaxf(u, 0.f); mb[2 * k + 1] = fmaxf(v, 0.f);
        }
        const u64* pr2 = (const u64*)(s_prog + t * 16);
        #pragma unroll
        for (int k = 0; k < 8; ++k) {
            u64 p = pr2[k];
            Ra[k] = fma2(pk(ma[2 * k], ma[2 * k + 1]), p, Ra[k]);
            Rb[k] = fma2(pk(mb[2 * k], mb[2 * k + 1]), p, Rb[k]);
        }
        const float* Pt = region0 + t * 272;
        #pragma unroll
        for (int j = 0; j < 17; ++j) {
            u64 mja = (j < 16) ? pk(ma[j], ma[j]) : one2;
            u64 mjb = (j < 16) ? pk(mb[j], mb[j]) : one2;
            const ulonglong2* prow = (const ulonglong2*)(Pt + j * 16);
            #pragma unroll
            for (int kk = 0; kk < 4; ++kk) {
                ulonglong2 p = prow[kk];
                za[2 * kk]     = fma2(mja, p.x, za[2 * kk]);
                za[2 * kk + 1] = fma2(mja, p.y, za[2 * kk + 1]);
                zb[2 * kk]     = fma2(mjb, p.x, zb[2 * kk]);
                zb[2 * kk + 1] = fma2(mjb, p.y, zb[2 * kk + 1]);
            }
        }
    }

    // ---- phase C for both row groups ----
    phaseC(xa, oa, region0, s_wupc, s_bu, Ra, tid);
    phaseC(xb, ob, region0, s_wupc, s_bu, Rb, tid);
}

extern "C" void kernel_launch(void* const* d_in, const int* in_sizes, int n_in,
                              void* d_out, int out_size) {
    const float* x    = (const float*)d_in[0];
    const float* prog = (const float*)d_in[1];
    const float* wd   = (const float*)d_in[2];
    const float* bd   = (const float*)d_in[3];
    const float* wu   = (const float*)d_in[4];
    const float* bu   = (const float*)d_in[5];
    float* out = (float*)d_out;

    cudaFuncSetAttribute(proc_kernel,
                         cudaFuncAttributeMaxDynamicSharedMemorySize, SMEM_BYTES);

    setup_kernel<<<1, 256>>>(prog, wd, bd, wu, bu);

    int rows = in_sizes[0] / HDIM;          // 262144
    int blocks = rows / 512;                // 512
    proc_kernel<<<blocks, 256, SMEM_BYTES>>>(x, out);
}

// round 6
// speedup vs baseline: 1.2077x; 1.2077x over previous
#include <cuda_runtime.h>
#include <cstdint>

// ProcessorNet reduction (exact up to fp reassociation):
//   z_0 = x@wd.T + bd                              [B,16]
//   z_{t+1} = z_t + relu(z_t) @ P_t + c,  P_t = diag(prog_t) @ A,  A = wu.T@wd.T
//   R = sum_t relu(z_t)*prog_t ;  out = x + R@wu.T + 64*bu
// ONE row per thread; z packed column-wise as 8x f32x2 (fma.rn.f32x2).
// P (c folded as 17th row) lives in __constant__ for steps 0..59 (uniform
// LDCU path, off the L1/LDS pipe); steps 60..63 + prog come from smem.

#define HDIM 128
#define LSTEPS 64

struct Consts {
    float Pc[LSTEPS][17][16];  // Pc[t][j][i]=prog[t][j]*A[j][i]; row16 = c
    float wd2[128][16];        // wd2[h][i] = wd[i][h]
    float prog[LSTEPS][16];
    float wupc[64][16][2];     // wupc[hp][j] = {wu[2hp][j], wu[2hp+1][j]}
    float bd[16];
    float bu64[128];           // 64*bu[h]
    float A[16][16];           // scratch
    float c[16];               // scratch
};
__device__ Consts g_c;

// First 60 steps of Pc in constant memory: 60*17*16*4 = 65280 bytes (< 64KB).
__constant__ ulonglong2 cPc[60][17][4];

// shared layout (floats):
//   tile 256*33 = 8448 | ptail 4*272 = 1088 | persist 5264
#define TILE_FLOATS 8448
#define PTAIL_FLOATS 1088
#define PERSIST_FLOATS 5264
#define SMEM_FLOATS (TILE_FLOATS + PTAIL_FLOATS + PERSIST_FLOATS)  // 14800
#define SMEM_BYTES (SMEM_FLOATS * 4)                               // 59200

__global__ void setup_kernel(const float* __restrict__ prog,
                             const float* __restrict__ wd,
                             const float* __restrict__ bd,
                             const float* __restrict__ wu,
                             const float* __restrict__ bu) {
    int tid = threadIdx.x;  // 256 threads, 1 block
    {   // A[j][i] = sum_h wu[h][j] * wd[i][h]
        int j = tid >> 4, i = tid & 15;
        float s = 0.f;
        #pragma unroll 8
        for (int h = 0; h < HDIM; ++h) s += wu[h * 16 + j] * wd[i * HDIM + h];
        g_c.A[j][i] = s;
    }
    if (tid < 16) {
        int i = tid;
        float s = 0.f;
        #pragma unroll 8
        for (int h = 0; h < HDIM; ++h) s += bu[h] * wd[i * HDIM + h];
        g_c.c[i] = s;
        g_c.bd[i] = bd[i];
    }
    for (int idx = tid; idx < LSTEPS * 16; idx += 256)
        g_c.prog[idx >> 4][idx & 15] = prog[idx];
    for (int idx = tid; idx < 128 * 16; idx += 256) {
        int h = idx >> 4, i = idx & 15;
        g_c.wd2[h][i] = wd[i * HDIM + h];
    }
    for (int idx = tid; idx < 64 * 16; idx += 256) {
        int hp = idx >> 4, j = idx & 15;
        g_c.wupc[hp][j][0] = wu[(2 * hp) * 16 + j];
        g_c.wupc[hp][j][1] = wu[(2 * hp + 1) * 16 + j];
    }
    for (int idx = tid; idx < 128; idx += 256) g_c.bu64[idx] = 64.f * bu[idx];
    __syncthreads();
    for (int idx = tid; idx < LSTEPS * 17 * 16; idx += 256) {
        int t = idx / 272, rem = idx % 272;
        int j = rem >> 4, i = rem & 15;
        g_c.Pc[t][j][i] = (j < 16) ? g_c.prog[t][j] * g_c.A[j][i] : g_c.c[i];
    }
}

// ---- packed f32x2 helpers ----
typedef unsigned long long u64;

__device__ __forceinline__ u64 pk(float x, float y) {
    u64 r; asm("mov.b64 %0, {%1, %2};" : "=l"(r) : "f"(x), "f"(y)); return r;
}
__device__ __forceinline__ void upk(u64 v, float& x, float& y) {
    asm("mov.b64 {%0, %1}, %2;" : "=f"(x), "=f"(y) : "l"(v));
}
__device__ __forceinline__ u64 fma2(u64 a, u64 b, u64 c) {
    u64 d; asm("fma.rn.f32x2 %0, %1, %2, %3;" : "=l"(d) : "l"(a), "l"(b), "l"(c)); return d;
}

__global__ __launch_bounds__(256, 3)
void proc_kernel(const float* __restrict__ x, float* __restrict__ out) {
    extern __shared__ float sm[];
    float* tile    = sm;                       // 8448
    float* s_ptail = sm + TILE_FLOATS;         // 1088
    float* s_wd2   = s_ptail + PTAIL_FLOATS;   // 2048
    float* s_prog  = s_wd2 + 2048;             // 1024
    float* s_wupc  = s_prog + 1024;            // 2048
    float* s_bd    = s_wupc + 2048;            // 16
    float* s_bu    = s_bd + 16;                // 128

    int tid = threadIdx.x;

    // copy persistent consts (wd2..bu64 contiguous in Consts) + P tail
    {
        const float4* src = (const float4*)&g_c.wd2[0][0];
        float4* dst = (float4*)s_wd2;
        for (int i = tid; i < PERSIST_FLOATS / 4; i += 256) dst[i] = src[i];
        const float4* ps = (const float4*)&g_c.Pc[60][0][0];
        float4* pd = (float4*)s_ptail;
        for (int i = tid; i < PTAIL_FLOATS / 4; i += 256) pd[i] = ps[i];
    }
    __syncthreads();

    long row0 = (long)blockIdx.x * 256;
    const float* xr = x + row0 * HDIM;
    float* outr = out + row0 * HDIM;

    u64 z2[8];
    #pragma unroll
    for (int k = 0; k < 8; ++k) z2[k] = *(const u64*)(s_bd + 2 * k);

    // ---- phase A: z = x @ wd.T + bd (x staged via coalesced smem tile) ----
    for (int ch = 0; ch < 4; ++ch) {
        __syncthreads();
        for (int f = tid; f < 8192; f += 256) {
            int r = f >> 5, c = f & 31;
            tile[r * 33 + c] = xr[(long)r * HDIM + ch * 32 + c];
        }
        __syncthreads();
        #pragma unroll
        for (int c = 0; c < 32; ++c) {
            float xv = tile[tid * 33 + c];
            u64 xs = pk(xv, xv);
            const ulonglong2* w = (const ulonglong2*)(s_wd2 + (ch * 32 + c) * 16);
            #pragma unroll
            for (int kk = 0; kk < 4; ++kk) {
                ulonglong2 wv = w[kk];
                z2[2 * kk]     = fma2(xs, wv.x, z2[2 * kk]);
                z2[2 * kk + 1] = fma2(xs, wv.y, z2[2 * kk + 1]);
            }
        }
    }

    // ---- phase B: 64-step recurrence; P from constant (0..59), smem tail ----
    u64 Racc2[8];
    #pragma unroll
    for (int k = 0; k < 8; ++k) Racc2[k] = 0ull;
    const u64 one2 = pk(1.f, 1.f);

    #pragma unroll 1
    for (int t = 0; t < 60; ++t) {
        float m[16];
        #pragma unroll
        for (int k = 0; k < 8; ++k) {
            float u, v;
            upk(z2[k], u, v);
            m[2 * k] = fmaxf(u, 0.f); m[2 * k + 1] = fmaxf(v, 0.f);
        }
        const u64* pr2 = (const u64*)(s_prog + t * 16);
        #pragma unroll
        for (int k = 0; k < 8; ++k)
            Racc2[k] = fma2(pk(m[2 * k], m[2 * k + 1]), pr2[k], Racc2[k]);
        #pragma unroll
        for (int j = 0; j < 17; ++j) {
            u64 mj = (j < 16) ? pk(m[j], m[j]) : one2;
            ulonglong2 pa = cPc[t][j][0];
            ulonglong2 pb = cPc[t][j][1];
            ulonglong2 pc2 = cPc[t][j][2];
            ulonglong2 pd = cPc[t][j][3];
            z2[0] = fma2(mj, pa.x, z2[0]);  z2[1] = fma2(mj, pa.y, z2[1]);
            z2[2] = fma2(mj, pb.x, z2[2]);  z2[3] = fma2(mj, pb.y, z2[3]);
            z2[4] = fma2(mj, pc2.x, z2[4]); z2[5] = fma2(mj, pc2.y, z2[5]);
            z2[6] = fma2(mj, pd.x, z2[6]);  z2[7] = fma2(mj, pd.y, z2[7]);
        }
    }
    #pragma unroll 1
    for (int t = 60; t < 64; ++t) {
        float m[16];
        #pragma unroll
        for (int k = 0; k < 8; ++k) {
            float u, v;
            upk(z2[k], u, v);
            m[2 * k] = fmaxf(u, 0.f); m[2 * k + 1] = fmaxf(v, 0.f);
        }
        const u64* pr2 = (const u64*)(s_prog + t * 16);
        #pragma unroll
        for (int k = 0; k < 8; ++k)
            Racc2[k] = fma2(pk(m[2 * k], m[2 * k + 1]), pr2[k], Racc2[k]);
        const float* Pt = s_ptail + (t - 60) * 272;
        #pragma unroll
        for (int j = 0; j < 17; ++j) {
            u64 mj = (j < 16) ? pk(m[j], m[j]) : one2;
            const ulonglong2* prow = (const ulonglong2*)(Pt + j * 16);
            #pragma unroll
            for (int kk = 0; kk < 4; ++kk) {
                ulonglong2 p = prow[kk];
                z2[2 * kk]     = fma2(mj, p.x, z2[2 * kk]);
                z2[2 * kk + 1] = fma2(mj, p.y, z2[2 * kk + 1]);
            }
        }
    }

    // ---- phase C: out = x + R @ wu.T + 64*bu (staged through tile) ----
    u64 Rs[16];
    #pragma unroll
    for (int k = 0; k < 8; ++k) {
        float r0, r1;
        upk(Racc2[k], r0, r1);
        Rs[2 * k]     = pk(r0, r0);
        Rs[2 * k + 1] = pk(r1, r1);
    }

    for (int ch = 0; ch < 4; ++ch) {
        __syncthreads();
        #pragma unroll
        for (int hp = 0; hp < 16; ++hp) {
            int h2 = ch * 16 + hp;
            u64 acc = *(const u64*)(s_bu + h2 * 2);
            const ulonglong2* urow = (const ulonglong2*)(s_wupc + h2 * 32);
            #pragma unroll
            for (int jj = 0; jj < 8; ++jj) {
                ulonglong2 u = urow[jj];
                acc = fma2(Rs[2 * jj],     u.x, acc);
                acc = fma2(Rs[2 * jj + 1], u.y, acc);
            }
            float y0, y1;
            upk(acc, y0, y1);
            tile[tid * 33 + 2 * hp]     = y0;
            tile[tid * 33 + 2 * hp + 1] = y1;
        }
        __syncthreads();
        for (int f = tid; f < 8192; f += 256) {
            int r = f >> 5, c = f & 31;
            long g = (long)r * HDIM + ch * 32 + c;
            outr[g] = xr[g] + tile[r * 33 + c];
        }
    }
}

extern "C" void kernel_launch(void* const* d_in, const int* in_sizes, int n_in,
                              void* d_out, int out_size) {
    const float* x    = (const float*)d_in[0];
    const float* prog = (const float*)d_in[1];
    const float* wd   = (const float*)d_in[2];
    const float* bd   = (const float*)d_in[3];
    const float* wu   = (const float*)d_in[4];
    const float* bu   = (const float*)d_in[5];
    float* out = (float*)d_out;

    cudaFuncSetAttribute(proc_kernel,
                         cudaFuncAttributeMaxDynamicSharedMemorySize, SMEM_BYTES);

    setup_kernel<<<1, 256>>>(prog, wd, bd, wu, bu);

    // copy first 60 steps of Pc into constant memory (device-to-device,
    // async, graph-capturable)
    void* gc_ptr = nullptr;
    cudaGetSymbolAddress(&gc_ptr, g_c);   // Pc is at offset 0 of g_c
    cudaMemcpyToSymbolAsync(cPc, gc_ptr, 60 * 17 * 16 * sizeof(float), 0,
                            cudaMemcpyDeviceToDevice);

    int rows = in_sizes[0] / HDIM;          // 262144
    int blocks = rows / 256;                // 1024
    proc_kernel<<<blocks, 256, SMEM_BYTES>>>(x, out);
}